// round 1
// baseline (speedup 1.0000x reference)
#include <cuda_runtime.h>
#include <math.h>

// Problem constants
#define B_   4
#define T_   4096
#define D_   1024
#define H_   16
#define HD   64
#define BT   (B_*T_)      // 16384
#define BH   (B_*H_)      // 64
#define NKV  3072
#define NCHUNK 8          // T-chunks for kv accumulation
#define CHLEN (T_/NCHUNK) // 512

// Scratch (static device globals: allocation-free at launch time)
__device__ float g_qkv[BT*NKV];              // (B*T, 3*D)   201 MB
__device__ float g_qf [BH*T_*HD];            // (B*H, T, hd)  67 MB
__device__ float g_kf [BH*T_*HD];            //               67 MB
__device__ float g_kvp[NCHUNK*BH*HD*HD];     // partial kv     8 MB
__device__ float g_kv [BH*HD*HD];            //                1 MB
__device__ float g_ksp[NCHUNK*BH*HD];        // partial ksum
__device__ float g_ksum[BH*HD];
__device__ float g_attn[BT*D_];              //               67 MB
__device__ float g_cos[T_*32];
__device__ float g_sin[T_*32];

// ---------------------------------------------------------------------------
// RoPE table: angle = t * base^(-2i/64), computed in double for accuracy.
// ---------------------------------------------------------------------------
__global__ void rope_table_kernel() {
    int idx = blockIdx.x * blockDim.x + threadIdx.x;
    if (idx >= T_*32) return;
    int t = idx >> 5;
    int i = idx & 31;
    double inv = pow(500000.0, -(double)(2*i) / 64.0);
    double a = (double)t * inv;
    g_cos[idx] = (float)cos(a);
    g_sin[idx] = (float)sin(a);
}

// ---------------------------------------------------------------------------
// SGEMM: C[M,N] = A[M,K] @ B[K,N], all row-major, M%128==0, N%128==0, K%16==0
// 128x128 block tile, BK=16, 8x8 per-thread microtile, 256 threads.
// ---------------------------------------------------------------------------
#define BM 128
#define BN 128
#define BK 16
#define TM 8
#define TN 8

__global__ __launch_bounds__(256)
void sgemm_kernel(int M, int N, int K,
                  const float* __restrict__ A,
                  const float* __restrict__ B,
                  float* __restrict__ C) {
    __shared__ float As[BK][BM];   // A transposed: As[k][m]
    __shared__ float Bs[BK][BN];

    const int tid = threadIdx.x;
    const int tr  = tid >> 4;      // 0..15
    const int tc  = tid & 15;      // 0..15
    const int rowBase = blockIdx.y * BM;
    const int colBase = blockIdx.x * BN;

    // A tile: 128x16 = 512 float4 (along K); thread covers f = tid, tid+256
    const int aRow  = tid >> 2;    // 0..63
    const int aCol4 = tid & 3;     // 0..3
    // B tile: 16x128 = 512 float4 (along N)
    const int bRow  = tid >> 5;    // 0..7
    const int bCol4 = tid & 31;    // 0..31

    float acc[TM][TN] = {};
    float4 ra0, ra1, rb0, rb1;

    for (int k0 = 0; k0 < K; k0 += BK) {
        #pragma unroll
        for (int u = 0; u < 2; u++) {
            int r = aRow + u*64;
            float4 v = *(const float4*)&A[(size_t)(rowBase + r)*K + k0 + aCol4*4];
            As[aCol4*4+0][r] = v.x;
            As[aCol4*4+1][r] = v.y;
            As[aCol4*4+2][r] = v.z;
            As[aCol4*4+3][r] = v.w;
        }
        #pragma unroll
        for (int u = 0; u < 2; u++) {
            int r = bRow + u*8;
            float4 v = *(const float4*)&B[(size_t)(k0 + r)*N + colBase + bCol4*4];
            *(float4*)&Bs[r][bCol4*4] = v;
        }
        __syncthreads();

        #pragma unroll
        for (int k = 0; k < BK; k++) {
            ra0 = *(const float4*)&As[k][tr*TM + 0];
            ra1 = *(const float4*)&As[k][tr*TM + 4];
            rb0 = *(const float4*)&Bs[k][tc*TN + 0];
            rb1 = *(const float4*)&Bs[k][tc*TN + 4];
            float ra[TM] = {ra0.x, ra0.y, ra0.z, ra0.w, ra1.x, ra1.y, ra1.z, ra1.w};
            float rb[TN] = {rb0.x, rb0.y, rb0.z, rb0.w, rb1.x, rb1.y, rb1.z, rb1.w};
            #pragma unroll
            for (int i = 0; i < TM; i++)
                #pragma unroll
                for (int j = 0; j < TN; j++)
                    acc[i][j] += ra[i] * rb[j];
        }
        __syncthreads();
    }

    #pragma unroll
    for (int i = 0; i < TM; i++) {
        size_t r = (size_t)(rowBase + tr*TM + i);
        #pragma unroll
        for (int j4 = 0; j4 < TN/4; j4++) {
            float4 v = make_float4(acc[i][j4*4+0], acc[i][j4*4+1],
                                   acc[i][j4*4+2], acc[i][j4*4+3]);
            *(float4*)&C[r*N + colBase + tc*TN + j4*4] = v;
        }
    }
}

// ---------------------------------------------------------------------------
// RoPE + feature map: reads g_qkv (B,T,3,H,hd), writes g_qf/g_kf (B,H,T,hd).
// Thread handles one (b,t,h,i) with i in [0,32): pair (i, i+32).
// qf = elu(q_rot * 0.125)+1 ; kf = elu(k_rot)+1 ; elu(x)+1 = x>0 ? x+1 : exp(x)
// ---------------------------------------------------------------------------
__global__ __launch_bounds__(256)
void rope_feat_kernel() {
    int idx = blockIdx.x * 256 + threadIdx.x;   // B*T*H*32 = 8388608
    int i  = idx & 31;
    int h  = (idx >> 5) & 15;
    int bt = idx >> 9;                          // 0..16383
    int t  = bt & (T_-1);
    int b  = bt >> 12;

    float c = g_cos[t*32 + i];
    float s = g_sin[t*32 + i];

    int base = bt*NKV + h*HD;
    float q1 = g_qkv[base + i];
    float q2 = g_qkv[base + 32 + i];
    float k1 = g_qkv[base + 1024 + i];
    float k2 = g_qkv[base + 1024 + 32 + i];

    float qr1 = q1*c - q2*s;
    float qr2 = q2*c + q1*s;
    float kr1 = k1*c - k2*s;
    float kr2 = k2*c + k1*s;

    qr1 *= 0.125f; qr2 *= 0.125f;
    float qf1 = qr1 > 0.f ? qr1 + 1.f : expf(qr1);
    float qf2 = qr2 > 0.f ? qr2 + 1.f : expf(qr2);
    float kf1 = kr1 > 0.f ? kr1 + 1.f : expf(kr1);
    float kf2 = kr2 > 0.f ? kr2 + 1.f : expf(kr2);

    int ob = ((b*H_ + h)*T_ + t)*HD;
    g_qf[ob + i]      = qf1;
    g_qf[ob + 32 + i] = qf2;
    g_kf[ob + i]      = kf1;
    g_kf[ob + 32 + i] = kf2;
}

// ---------------------------------------------------------------------------
// kv partial accumulation: block = (bh, chunk). kv[d][j] += kf[t,d]*v[t,j].
// Thread owns (d = tid>>2, j in [(tid&3)*16, +16)). Deterministic partials.
// ---------------------------------------------------------------------------
__global__ __launch_bounds__(256)
void kv_accum_kernel() {
    int blk = blockIdx.x;            // bh*NCHUNK + c
    int bh  = blk >> 3;
    int c   = blk & 7;
    int b   = bh >> 4;
    int h   = bh & 15;
    int tid = threadIdx.x;
    int d   = tid >> 2;
    int jb  = (tid & 3) << 4;

    __shared__ float kbuf[8][64];
    __shared__ float vbuf[8][64];

    float acc[16];
    #pragma unroll
    for (int j = 0; j < 16; j++) acc[j] = 0.f;
    float ks = 0.f;

    int t0 = c * CHLEN;
    for (int tb = 0; tb < CHLEN; tb += 8) {
        #pragma unroll
        for (int u = 0; u < 2; u++) {
            int li = tid + u*256;
            int tt = li >> 6, dd = li & 63;
            int t  = t0 + tb + tt;
            kbuf[tt][dd] = g_kf[(bh*T_ + t)*HD + dd];
            vbuf[tt][dd] = g_qkv[(size_t)(b*T_ + t)*NKV + 2048 + h*HD + dd];
        }
        __syncthreads();
        #pragma unroll
        for (int tt = 0; tt < 8; tt++) {
            float kd = kbuf[tt][d];
            ks += kd;
            const float4* v4 = (const float4*)&vbuf[tt][jb];
            #pragma unroll
            for (int j4 = 0; j4 < 4; j4++) {
                float4 vv = v4[j4];
                acc[j4*4+0] += kd * vv.x;
                acc[j4*4+1] += kd * vv.y;
                acc[j4*4+2] += kd * vv.z;
                acc[j4*4+3] += kd * vv.w;
            }
        }
        __syncthreads();
    }

    int ob = ((c*BH + bh)*HD + d)*HD + jb;
    #pragma unroll
    for (int j = 0; j < 16; j++) g_kvp[ob + j] = acc[j];
    if ((tid & 3) == 0) g_ksp[(c*BH + bh)*HD + d] = ks;
}

// Fixed-order reduction of partials (deterministic).
__global__ void kv_reduce_kernel() {
    int idx = blockIdx.x * 256 + threadIdx.x;    // BH*HD*HD = 262144
    if (idx < BH*HD*HD) {
        float s = 0.f;
        #pragma unroll
        for (int c = 0; c < NCHUNK; c++) s += g_kvp[c*BH*HD*HD + idx];
        g_kv[idx] = s;
    }
    if (idx < BH*HD) {
        float s = 0.f;
        #pragma unroll
        for (int c = 0; c < NCHUNK; c++) s += g_ksp[c*BH*HD + idx];
        g_ksum[idx] = s;
    }
}

// ---------------------------------------------------------------------------
// out[t,j] = (sum_d qf[t,d]*kv[d,j]) / max(sum_d qf[t,d]*ksum[d], 1e-6)
// Block = (bh, t-chunk of 64). Thread owns (t_local = tid>>2, 16 j's).
// ---------------------------------------------------------------------------
__global__ __launch_bounds__(256)
void attn_out_kernel() {
    int blk = blockIdx.x;            // bh*64 + tc
    int bh  = blk >> 6;
    int tc  = blk & 63;
    int b   = bh >> 4;
    int h   = bh & 15;
    int tid = threadIdx.x;

    __shared__ float skv[HD*HD];
    __shared__ float sks[HD];
    __shared__ float sqf[64*HD];

    #pragma unroll
    for (int u = 0; u < 16; u++) {
        int li = tid + u*256;
        skv[li] = g_kv[bh*HD*HD + li];
        sqf[li] = g_qf[(bh*T_ + tc*64)*HD + li];
    }
    if (tid < 64) sks[tid] = g_ksum[bh*HD + tid];
    __syncthreads();

    int tl = tid >> 2;
    int jb = (tid & 3) << 4;

    float den = 0.f;
    #pragma unroll
    for (int dd = 0; dd < 64; dd++) den += sqf[tl*64 + dd] * sks[dd];
    float sc = 1.f / fmaxf(den, 1e-6f);

    float4 acc[4] = {};
    #pragma unroll
    for (int dd = 0; dd < 64; dd++) {
        float qd = sqf[tl*64 + dd];
        const float4* kvr = (const float4*)&skv[dd*64 + jb];
        #pragma unroll
        for (int j4 = 0; j4 < 4; j4++) {
            float4 kk = kvr[j4];
            acc[j4].x += qd * kk.x;
            acc[j4].y += qd * kk.y;
            acc[j4].z += qd * kk.z;
            acc[j4].w += qd * kk.w;
        }
    }

    int t = tc*64 + tl;
    float* outp = &g_attn[(size_t)(b*T_ + t)*D_ + h*HD + jb];
    #pragma unroll
    for (int j4 = 0; j4 < 4; j4++) {
        float4 v = make_float4(acc[j4].x*sc, acc[j4].y*sc, acc[j4].z*sc, acc[j4].w*sc);
        *(float4*)&outp[j4*4] = v;
    }
}

// ---------------------------------------------------------------------------
extern "C" void kernel_launch(void* const* d_in, const int* in_sizes, int n_in,
                              void* d_out, int out_size) {
    // Defensive input mapping by element count.
    const float* x = nullptr; const float* Wqkv = nullptr; const float* Wout = nullptr;
    for (int i = 0; i < n_in; i++) {
        if (in_sizes[i] == BT*D_)      x    = (const float*)d_in[i];
        else if (in_sizes[i] == D_*NKV) Wqkv = (const float*)d_in[i];
        else if (in_sizes[i] == D_*D_)  Wout = (const float*)d_in[i];
    }
    float* out = (float*)d_out;

    float *qkv_p, *attn_p;
    cudaGetSymbolAddress((void**)&qkv_p,  g_qkv);
    cudaGetSymbolAddress((void**)&attn_p, g_attn);

    // 1. RoPE tables
    rope_table_kernel<<<(T_*32 + 255)/256, 256>>>();

    // 2. qkv = x @ W_qkv   (16384 x 3072 x 1024)
    {
        dim3 grid(NKV/BN, BT/BM);
        sgemm_kernel<<<grid, 256>>>(BT, NKV, D_, x, Wqkv, qkv_p);
    }

    // 3. RoPE + feature maps
    rope_feat_kernel<<<(B_*T_*H_*32)/256, 256>>>();

    // 4. kv & ksum accumulation (chunked partials) + reduce
    kv_accum_kernel<<<BH*NCHUNK, 256>>>();
    kv_reduce_kernel<<<(BH*HD*HD)/256, 256>>>();

    // 5. attention epilogue -> g_attn (B,T,D)
    attn_out_kernel<<<BH*64, 256>>>();

    // 6. out = attn @ W_out  (16384 x 1024 x 1024)
    {
        dim3 grid(D_/BN, BT/BM);
        sgemm_kernel<<<grid, 256>>>(BT, D_, D_, attn_p, Wout, out);
    }
}

// round 3
// speedup vs baseline: 2.2764x; 2.2764x over previous
#include <cuda_runtime.h>
#include <math.h>
#include <stdint.h>

// Problem constants
#define B_   4
#define T_   4096
#define D_   1024
#define H_   16
#define HD   64
#define BT   (B_*T_)      // 16384
#define BH   (B_*H_)      // 64
#define NKV  3072
#define NCHUNK 16
#define CHLEN (T_/NCHUNK) // 256
#define GK   1024         // K of both GEMMs

// Scratch
__device__ float g_qkv[BT*NKV];
__device__ float g_qf [BH*T_*HD];
__device__ float g_kf [BH*T_*HD];
__device__ float g_kvp[NCHUNK*BH*HD*HD];
__device__ float g_kv [BH*HD*HD];
__device__ float g_ksp[NCHUNK*BH*HD];
__device__ float g_ksum[BH*HD];
__device__ float g_attn[BT*D_];
__device__ float g_xa  [BT*D_];      // tf32-rounded x
__device__ float g_wqT [NKV*D_];     // Wqkv^T, tf32-rounded
__device__ float g_woT [D_*D_];      // Wout^T, tf32-rounded
__device__ float g_cos[T_*32];
__device__ float g_sin[T_*32];

// ---------------------------------------------------------------------------
// helpers
// ---------------------------------------------------------------------------
__device__ __forceinline__ uint32_t smem_u32(const void* p) {
    uint32_t a;
    asm("{ .reg .u64 t; cvta.to.shared.u64 t, %1; cvt.u32.u64 %0, t; }"
        : "=r"(a) : "l"(p));
    return a;
}
__device__ __forceinline__ float tf32r(float x) {
    uint32_t o;
    asm("cvt.rna.tf32.f32 %0, %1;" : "=r"(o) : "f"(x));
    return __uint_as_float(o);
}
#define CP_ASYNC16(dst, src) \
    asm volatile("cp.async.cg.shared.global [%0], [%1], 16;" :: "r"(dst), "l"(src) : "memory")
#define CP_COMMIT()  asm volatile("cp.async.commit_group;" ::: "memory")
#define CP_WAIT1()   asm volatile("cp.async.wait_group 1;" ::: "memory")

__device__ __forceinline__ void mma_tf32(float* d, const float* a, const float* b) {
    asm volatile(
        "mma.sync.aligned.m16n8k8.row.col.f32.tf32.tf32.f32 "
        "{%0,%1,%2,%3}, {%4,%5,%6,%7}, {%8,%9}, {%0,%1,%2,%3};"
        : "+f"(d[0]), "+f"(d[1]), "+f"(d[2]), "+f"(d[3])
        : "r"(__float_as_uint(a[0])), "r"(__float_as_uint(a[1])),
          "r"(__float_as_uint(a[2])), "r"(__float_as_uint(a[3])),
          "r"(__float_as_uint(b[0])), "r"(__float_as_uint(b[1])));
}

// ---------------------------------------------------------------------------
// tf32 mma.sync GEMM: C[16384][N] = A[16384][1024] @ Bt[N][1024]^T
// 128x128 tile, BK=16, 3-stage cp.async pipeline, 256 threads (8 warps),
// warp tile 32(M) x 64(N): 2 m-tiles x 8 n-tiles of m16n8k8.
// SMEM: As[s][128][20], Bs[s][128][20] (padded rows: conflict-free frags)
// ---------------------------------------------------------------------------
#define STAGES 3
#define ROWF   20                       // floats per padded row
#define STG_F  (128*ROWF)               // floats per tile per stage
#define GEMM_SMEM (2*STAGES*STG_F*4)    // 61440 B

__global__ __launch_bounds__(256, 2)
void gemm_tf32_kernel(int N, const float* __restrict__ A,
                      const float* __restrict__ Bt, float* __restrict__ C) {
    extern __shared__ float sm[];
    float* As = sm;
    float* Bs = sm + STAGES*STG_F;

    const int tid  = threadIdx.x;
    const int wid  = tid >> 5;
    const int lane = tid & 31;
    const int g    = lane >> 2;     // groupID 0..7
    const int tg   = lane & 3;      // 0..3

    const int rowBase = blockIdx.y * 128;
    const int colBase = blockIdx.x * 128;
    const int mBase = (wid & 3) * 32;
    const int nBase = (wid >> 2) * 64;

    // cp.async mapping: thread -> row lr (0..127), 32B half (lc = 0 or 8 floats)
    const int lr = tid >> 1;
    const int lc = (tid & 1) * 8;
    const float* aSrc = A  + (size_t)(rowBase + lr)*GK + lc;
    const float* bSrc = Bt + (size_t)(colBase + lr)*GK + lc;
    const uint32_t aDst = smem_u32(As) + (uint32_t)(lr*ROWF + lc)*4;
    const uint32_t bDst = smem_u32(Bs) + (uint32_t)(lr*ROWF + lc)*4;

    float acc[2][8][4];
    #pragma unroll
    for (int mt = 0; mt < 2; mt++)
        #pragma unroll
        for (int nt = 0; nt < 8; nt++)
            #pragma unroll
            for (int q = 0; q < 4; q++) acc[mt][nt][q] = 0.f;

    // prologue: stages 0,1
    #pragma unroll
    for (int s = 0; s < STAGES-1; s++) {
        const uint32_t so = (uint32_t)s * (STG_F*4);
        const float* ap = aSrc + s*16;
        const float* bp = bSrc + s*16;
        CP_ASYNC16(aDst + so,      ap);
        CP_ASYNC16(aDst + so + 16, ap + 4);
        CP_ASYNC16(bDst + so,      bp);
        CP_ASYNC16(bDst + so + 16, bp + 4);
        CP_COMMIT();
    }

    const int NIT = GK / 16;   // 64
    for (int it = 0; it < NIT; it++) {
        CP_WAIT1();
        __syncthreads();

        // issue loads for it+2 (overwrites stage consumed at it-1; barrier above
        // guarantees every thread finished compute(it-1))
        const int nit = it + STAGES - 1;
        if (nit < NIT) {
            const int s = nit % STAGES;
            const uint32_t so = (uint32_t)s * (STG_F*4);
            const float* ap = aSrc + nit*16;
            const float* bp = bSrc + nit*16;
            CP_ASYNC16(aDst + so,      ap);
            CP_ASYNC16(aDst + so + 16, ap + 4);
            CP_ASYNC16(bDst + so,      bp);
            CP_ASYNC16(bDst + so + 16, bp + 4);
        }
        CP_COMMIT();

        // compute stage it%STAGES
        const float* a_ = As + (it % STAGES)*STG_F;
        const float* b_ = Bs + (it % STAGES)*STG_F;
        #pragma unroll
        for (int ks = 0; ks < 16; ks += 8) {
            float af[2][4];
            float bf[8][2];
            #pragma unroll
            for (int mt = 0; mt < 2; mt++) {
                const int r0 = mBase + mt*16 + g;
                af[mt][0] = a_[ r0     *ROWF + ks + tg    ];
                af[mt][1] = a_[(r0+8)  *ROWF + ks + tg    ];
                af[mt][2] = a_[ r0     *ROWF + ks + tg + 4];
                af[mt][3] = a_[(r0+8)  *ROWF + ks + tg + 4];
            }
            #pragma unroll
            for (int nt = 0; nt < 8; nt++) {
                const int c0 = nBase + nt*8 + g;
                bf[nt][0] = b_[c0*ROWF + ks + tg    ];
                bf[nt][1] = b_[c0*ROWF + ks + tg + 4];
            }
            #pragma unroll
            for (int mt = 0; mt < 2; mt++)
                #pragma unroll
                for (int nt = 0; nt < 8; nt++)
                    mma_tf32(acc[mt][nt], af[mt], bf[nt]);
        }
    }

    // epilogue
    #pragma unroll
    for (int mt = 0; mt < 2; mt++) {
        const int r0 = rowBase + mBase + mt*16 + g;
        #pragma unroll
        for (int nt = 0; nt < 8; nt++) {
            const int c0 = colBase + nBase + nt*8 + tg*2;
            *(float2*)&C[(size_t) r0   *N + c0] = make_float2(acc[mt][nt][0], acc[mt][nt][1]);
            *(float2*)&C[(size_t)(r0+8)*N + c0] = make_float2(acc[mt][nt][2], acc[mt][nt][3]);
        }
    }
}

// ---------------------------------------------------------------------------
// RoPE table
// ---------------------------------------------------------------------------
__global__ void rope_table_kernel() {
    int idx = blockIdx.x * blockDim.x + threadIdx.x;
    if (idx >= T_*32) return;
    int t = idx >> 5;
    int i = idx & 31;
    double inv = pow(500000.0, -(double)(2*i) / 64.0);
    double a = (double)t * inv;
    g_cos[idx] = (float)cos(a);
    g_sin[idx] = (float)sin(a);
}

// ---------------------------------------------------------------------------
// elementwise tf32 round: x -> g_xa
// ---------------------------------------------------------------------------
__global__ __launch_bounds__(256)
void round_x_kernel(const float* __restrict__ x) {
    int i = blockIdx.x * 256 + threadIdx.x;
    float4 v = ((const float4*)x)[i];
    v.x = tf32r(v.x); v.y = tf32r(v.y); v.z = tf32r(v.z); v.w = tf32r(v.w);
    ((float4*)g_xa)[i] = v;
}

// ---------------------------------------------------------------------------
// transpose + tf32 round: in[R][Cc] -> out[Cc][R]
// ---------------------------------------------------------------------------
__global__ __launch_bounds__(256)
void transpose_round_kernel(const float* __restrict__ in, float* __restrict__ out,
                            int R, int Cc) {
    __shared__ float tile[32][33];
    int bx = blockIdx.x * 32, by = blockIdx.y * 32;
    int tx = threadIdx.x, ty = threadIdx.y;       // block (32, 8)
    #pragma unroll
    for (int i = 0; i < 32; i += 8)
        tile[ty + i][tx] = in[(size_t)(by + ty + i) * Cc + bx + tx];
    __syncthreads();
    #pragma unroll
    for (int i = 0; i < 32; i += 8)
        out[(size_t)(bx + ty + i) * R + by + tx] = tf32r(tile[tx][ty + i]);
}

// ---------------------------------------------------------------------------
// RoPE + feature maps
// ---------------------------------------------------------------------------
__global__ __launch_bounds__(256)
void rope_feat_kernel() {
    int idx = blockIdx.x * 256 + threadIdx.x;
    int i  = idx & 31;
    int h  = (idx >> 5) & 15;
    int bt = idx >> 9;
    int t  = bt & (T_-1);
    int b  = bt >> 12;

    float c = g_cos[t*32 + i];
    float s = g_sin[t*32 + i];

    int base = bt*NKV + h*HD;
    float q1 = g_qkv[base + i];
    float q2 = g_qkv[base + 32 + i];
    float k1 = g_qkv[base + 1024 + i];
    float k2 = g_qkv[base + 1024 + 32 + i];

    float qr1 = q1*c - q2*s;
    float qr2 = q2*c + q1*s;
    float kr1 = k1*c - k2*s;
    float kr2 = k2*c + k1*s;

    qr1 *= 0.125f; qr2 *= 0.125f;
    float qf1 = qr1 > 0.f ? qr1 + 1.f : expf(qr1);
    float qf2 = qr2 > 0.f ? qr2 + 1.f : expf(qr2);
    float kf1 = kr1 > 0.f ? kr1 + 1.f : expf(kr1);
    float kf2 = kr2 > 0.f ? kr2 + 1.f : expf(kr2);

    int ob = ((b*H_ + h)*T_ + t)*HD;
    g_qf[ob + i]      = qf1;
    g_qf[ob + 32 + i] = qf2;
    g_kf[ob + i]      = kf1;
    g_kf[ob + 32 + i] = kf2;
}

// ---------------------------------------------------------------------------
// kv partial accumulation: 64 threads, 8x8 register microtile per thread.
// ---------------------------------------------------------------------------
__global__ __launch_bounds__(64)
void kv_accum_kernel() {
    int blk = blockIdx.x;
    int bh  = blk >> 4;
    int c   = blk & 15;
    int b   = bh >> 4;
    int h   = bh & 15;
    int tid = threadIdx.x;
    int d0  = (tid >> 3) * 8;
    int j0  = (tid & 7) * 8;

    __shared__ float kb[16][64];
    __shared__ float vb[16][64];

    float acc[8][8] = {};
    float ks[8] = {};

    int t0 = c * CHLEN;
    for (int tb = 0; tb < CHLEN; tb += 16) {
        #pragma unroll
        for (int u = 0; u < 4; u++) {
            int f  = tid + u*64;
            int rr = f >> 4, c4 = f & 15;
            int t  = t0 + tb + rr;
            *(float4*)&kb[rr][c4*4] =
                *(const float4*)&g_kf[((size_t)bh*T_ + t)*HD + c4*4];
            *(float4*)&vb[rr][c4*4] =
                *(const float4*)&g_qkv[((size_t)(b*T_ + t))*NKV + 2048 + h*HD + c4*4];
        }
        __syncthreads();
        #pragma unroll
        for (int tt = 0; tt < 16; tt++) {
            float kk[8], vv[8];
            *(float4*)&kk[0] = *(float4*)&kb[tt][d0];
            *(float4*)&kk[4] = *(float4*)&kb[tt][d0+4];
            *(float4*)&vv[0] = *(float4*)&vb[tt][j0];
            *(float4*)&vv[4] = *(float4*)&vb[tt][j0+4];
            #pragma unroll
            for (int i = 0; i < 8; i++) {
                ks[i] += kk[i];
                #pragma unroll
                for (int j = 0; j < 8; j++)
                    acc[i][j] += kk[i] * vv[j];
            }
        }
        __syncthreads();
    }

    #pragma unroll
    for (int i = 0; i < 8; i++) {
        float* p = &g_kvp[((size_t)(c*BH + bh)*HD + d0 + i)*HD + j0];
        #pragma unroll
        for (int j4 = 0; j4 < 2; j4++)
            *(float4*)&p[j4*4] = make_float4(acc[i][j4*4+0], acc[i][j4*4+1],
                                             acc[i][j4*4+2], acc[i][j4*4+3]);
    }
    if ((tid & 7) == 0) {
        #pragma unroll
        for (int i = 0; i < 8; i++)
            g_ksp[(c*BH + bh)*HD + d0 + i] = ks[i];
    }
}

__global__ void kv_reduce_kernel() {
    int idx = blockIdx.x * 256 + threadIdx.x;
    if (idx < BH*HD*HD) {
        float s = 0.f;
        #pragma unroll
        for (int c = 0; c < NCHUNK; c++) s += g_kvp[(size_t)c*BH*HD*HD + idx];
        g_kv[idx] = s;
    }
    if (idx < BH*HD) {
        float s = 0.f;
        #pragma unroll
        for (int c = 0; c < NCHUNK; c++) s += g_ksp[c*BH*HD + idx];
        g_ksum[idx] = s;
    }
}

// ---------------------------------------------------------------------------
// attention epilogue -> g_attn (tf32-rounded, feeds GEMM2)
// ---------------------------------------------------------------------------
__global__ __launch_bounds__(256)
void attn_out_kernel() {
    int blk = blockIdx.x;
    int bh  = blk >> 6;
    int tc  = blk & 63;
    int b   = bh >> 4;
    int h   = bh & 15;
    int tid = threadIdx.x;

    __shared__ float skv[HD*HD];
    __shared__ float sks[HD];
    __shared__ float sqf[64*HD];

    #pragma unroll
    for (int u = 0; u < 16; u++) {
        int li = tid + u*256;
        skv[li] = g_kv[bh*HD*HD + li];
        sqf[li] = g_qf[((size_t)bh*T_ + tc*64)*HD + li];
    }
    if (tid < 64) sks[tid] = g_ksum[bh*HD + tid];
    __syncthreads();

    int tl = tid >> 2;
    int jb = (tid & 3) << 4;

    float den = 0.f;
    #pragma unroll
    for (int dd = 0; dd < 64; dd++) den += sqf[tl*64 + dd] * sks[dd];
    float sc = 1.f / fmaxf(den, 1e-6f);

    float4 acc[4] = {};
    #pragma unroll
    for (int dd = 0; dd < 64; dd++) {
        float qd = sqf[tl*64 + dd];
        const float4* kvr = (const float4*)&skv[dd*64 + jb];
        #pragma unroll
        for (int j4 = 0; j4 < 4; j4++) {
            float4 kk = kvr[j4];
            acc[j4].x += qd * kk.x;
            acc[j4].y += qd * kk.y;
            acc[j4].z += qd * kk.z;
            acc[j4].w += qd * kk.w;
        }
    }

    int t = tc*64 + tl;
    float* outp = &g_attn[((size_t)(b*T_ + t))*D_ + h*HD + jb];
    #pragma unroll
    for (int j4 = 0; j4 < 4; j4++) {
        float4 v = make_float4(tf32r(acc[j4].x*sc), tf32r(acc[j4].y*sc),
                               tf32r(acc[j4].z*sc), tf32r(acc[j4].w*sc));
        *(float4*)&outp[j4*4] = v;
    }
}

// ---------------------------------------------------------------------------
extern "C" void kernel_launch(void* const* d_in, const int* in_sizes, int n_in,
                              void* d_out, int out_size) {
    const float* x = nullptr; const float* Wqkv = nullptr; const float* Wout = nullptr;
    for (int i = 0; i < n_in; i++) {
        if (in_sizes[i] == BT*D_)       x    = (const float*)d_in[i];
        else if (in_sizes[i] == D_*NKV) Wqkv = (const float*)d_in[i];
        else if (in_sizes[i] == D_*D_)  Wout = (const float*)d_in[i];
    }
    float* out = (float*)d_out;

    float *qkv_p, *attn_p, *xa_p, *wqT_p, *woT_p;
    cudaGetSymbolAddress((void**)&qkv_p,  g_qkv);
    cudaGetSymbolAddress((void**)&attn_p, g_attn);
    cudaGetSymbolAddress((void**)&xa_p,   g_xa);
    cudaGetSymbolAddress((void**)&wqT_p,  g_wqT);
    cudaGetSymbolAddress((void**)&woT_p,  g_woT);

    cudaFuncSetAttribute(gemm_tf32_kernel,
                         cudaFuncAttributeMaxDynamicSharedMemorySize, GEMM_SMEM);

    // 1. RoPE tables + input prep (tf32 rounding / weight transpose)
    rope_table_kernel<<<(T_*32 + 255)/256, 256>>>();
    round_x_kernel<<<(BT*D_/4)/256, 256>>>(x);
    {
        dim3 blk(32, 8);
        transpose_round_kernel<<<dim3(NKV/32, D_/32), blk>>>(Wqkv, wqT_p, D_, NKV);
        transpose_round_kernel<<<dim3(D_/32,  D_/32), blk>>>(Wout, woT_p, D_, D_);
    }

    // 2. qkv = x @ W_qkv (tf32 mma.sync)
    gemm_tf32_kernel<<<dim3(NKV/128, BT/128), 256, GEMM_SMEM>>>(NKV, xa_p, wqT_p, qkv_p);

    // 3. RoPE + feature maps
    rope_feat_kernel<<<(B_*T_*H_*32)/256, 256>>>();

    // 4. kv & ksum
    kv_accum_kernel<<<BH*NCHUNK, 64>>>();
    kv_reduce_kernel<<<(BH*HD*HD)/256, 256>>>();

    // 5. attention epilogue
    attn_out_kernel<<<BH*64, 256>>>();

    // 6. out = attn @ W_out (tf32 mma.sync)
    gemm_tf32_kernel<<<dim3(D_/128, BT/128), 256, GEMM_SMEM>>>(D_, attn_p, woT_p, out);
}

// round 4
// speedup vs baseline: 2.3346x; 1.0256x over previous
#include <cuda_runtime.h>
#include <math.h>
#include <stdint.h>

// Problem constants
#define B_   4
#define T_   4096
#define D_   1024
#define H_   16
#define HD   64
#define BT   (B_*T_)      // 16384
#define BH   (B_*H_)      // 64
#define NKV  3072
#define NCHUNK 16
#define CHLEN (T_/NCHUNK) // 256
#define GK   1024

// Scratch
__device__ float g_qf [BH*T_*HD];
__device__ float g_kf [BH*T_*HD];
__device__ float g_v  [BH*T_*HD];
__device__ float g_kvp[NCHUNK*BH*HD*HD];
__device__ float g_kv [BH*HD*HD];
__device__ float g_ksp[NCHUNK*BH*HD];
__device__ float g_ksum[BH*HD];
__device__ float g_attn[BT*D_];
__device__ float g_xa  [BT*D_];      // tf32-rounded x
__device__ float g_wqT [NKV*D_];     // Wqkv^T, tf32-rounded
__device__ float g_woT [D_*D_];      // Wout^T, tf32-rounded
__device__ float g_cos[T_*32];
__device__ float g_sin[T_*32];

// ---------------------------------------------------------------------------
__device__ __forceinline__ uint32_t smem_u32(const void* p) {
    uint32_t a;
    asm("{ .reg .u64 t; cvta.to.shared.u64 t, %1; cvt.u32.u64 %0, t; }"
        : "=r"(a) : "l"(p));
    return a;
}
__device__ __forceinline__ float tf32r(float x) {
    uint32_t o;
    asm("cvt.rna.tf32.f32 %0, %1;" : "=r"(o) : "f"(x));
    return __uint_as_float(o);
}
#define CP_ASYNC16(dst, src) \
    asm volatile("cp.async.cg.shared.global [%0], [%1], 16;" :: "r"(dst), "l"(src) : "memory")
#define CP_COMMIT()  asm volatile("cp.async.commit_group;" ::: "memory")
#define CP_WAIT2()   asm volatile("cp.async.wait_group 2;" ::: "memory")

__device__ __forceinline__ void mma_tf32(float* d, const float* a, const float* b) {
    asm volatile(
        "mma.sync.aligned.m16n8k8.row.col.f32.tf32.tf32.f32 "
        "{%0,%1,%2,%3}, {%4,%5,%6,%7}, {%8,%9}, {%0,%1,%2,%3};"
        : "+f"(d[0]), "+f"(d[1]), "+f"(d[2]), "+f"(d[3])
        : "r"(__float_as_uint(a[0])), "r"(__float_as_uint(a[1])),
          "r"(__float_as_uint(a[2])), "r"(__float_as_uint(a[3])),
          "r"(__float_as_uint(b[0])), "r"(__float_as_uint(b[1])));
}
__device__ __forceinline__ float elu1(float x) {
    return x > 0.f ? x + 1.f : expf(x);
}

// ---------------------------------------------------------------------------
// tf32 mma.sync GEMM: 128x128 tile, BK=16, 4-stage cp.async, 256 threads.
// Warp tile 32(M) x 64(N). mode 0: write C[M][N]. mode 1: fused qkv epilogue
// (RoPE + elu feature maps, scatter to g_qf/g_kf/g_v in (b,h,t,hd) layout).
// ---------------------------------------------------------------------------
#define STAGES 4
#define ROWF   20
#define STG_F  (128*ROWF)
#define GEMM_SMEM (2*STAGES*STG_F*4)    // 81920 B

__global__ __launch_bounds__(256, 2)
void gemm_tf32_kernel(int N, int mode, const float* __restrict__ A,
                      const float* __restrict__ Bt, float* __restrict__ C) {
    extern __shared__ float sm[];
    float* As = sm;
    float* Bs = sm + STAGES*STG_F;

    const int tid  = threadIdx.x;
    const int wid  = tid >> 5;
    const int lane = tid & 31;
    const int g    = lane >> 2;
    const int tg   = lane & 3;

    const int rowBase = blockIdx.y * 128;
    const int colBase = blockIdx.x * 128;
    const int mBase = (wid & 3) * 32;
    const int nBase = (wid >> 2) * 64;

    const int lr = tid >> 1;
    const int lc = (tid & 1) * 8;
    const float* aSrc = A  + (size_t)(rowBase + lr)*GK + lc;
    const float* bSrc = Bt + (size_t)(colBase + lr)*GK + lc;
    const uint32_t aDst = smem_u32(As) + (uint32_t)(lr*ROWF + lc)*4;
    const uint32_t bDst = smem_u32(Bs) + (uint32_t)(lr*ROWF + lc)*4;

    float acc[2][8][4];
    #pragma unroll
    for (int mt = 0; mt < 2; mt++)
        #pragma unroll
        for (int nt = 0; nt < 8; nt++)
            #pragma unroll
            for (int q = 0; q < 4; q++) acc[mt][nt][q] = 0.f;

    // prologue: stages 0..2
    #pragma unroll
    for (int s = 0; s < STAGES-1; s++) {
        const uint32_t so = (uint32_t)s * (STG_F*4);
        const float* ap = aSrc + s*16;
        const float* bp = bSrc + s*16;
        CP_ASYNC16(aDst + so,      ap);
        CP_ASYNC16(aDst + so + 16, ap + 4);
        CP_ASYNC16(bDst + so,      bp);
        CP_ASYNC16(bDst + so + 16, bp + 4);
        CP_COMMIT();
    }

    const int NIT = GK / 16;   // 64
    for (int it = 0; it < NIT; it++) {
        CP_WAIT2();
        __syncthreads();

        const int nit = it + STAGES - 1;
        if (nit < NIT) {
            const int s = nit % STAGES;
            const uint32_t so = (uint32_t)s * (STG_F*4);
            const float* ap = aSrc + nit*16;
            const float* bp = bSrc + nit*16;
            CP_ASYNC16(aDst + so,      ap);
            CP_ASYNC16(aDst + so + 16, ap + 4);
            CP_ASYNC16(bDst + so,      bp);
            CP_ASYNC16(bDst + so + 16, bp + 4);
        }
        CP_COMMIT();

        const float* a_ = As + (it % STAGES)*STG_F;
        const float* b_ = Bs + (it % STAGES)*STG_F;
        #pragma unroll
        for (int ks = 0; ks < 16; ks += 8) {
            float af[2][4];
            float bf[8][2];
            #pragma unroll
            for (int mt = 0; mt < 2; mt++) {
                const int r0 = mBase + mt*16 + g;
                af[mt][0] = a_[ r0    *ROWF + ks + tg    ];
                af[mt][1] = a_[(r0+8) *ROWF + ks + tg    ];
                af[mt][2] = a_[ r0    *ROWF + ks + tg + 4];
                af[mt][3] = a_[(r0+8) *ROWF + ks + tg + 4];
            }
            #pragma unroll
            for (int nt = 0; nt < 8; nt++) {
                const int c0 = nBase + nt*8 + g;
                bf[nt][0] = b_[c0*ROWF + ks + tg    ];
                bf[nt][1] = b_[c0*ROWF + ks + tg + 4];
            }
            #pragma unroll
            for (int mt = 0; mt < 2; mt++)
                #pragma unroll
                for (int nt = 0; nt < 8; nt++)
                    mma_tf32(acc[mt][nt], af[mt], bf[nt]);
        }
    }

    if (mode == 0) {
        // plain epilogue
        #pragma unroll
        for (int mt = 0; mt < 2; mt++) {
            const int r0 = rowBase + mBase + mt*16 + g;
            #pragma unroll
            for (int nt = 0; nt < 8; nt++) {
                const int c0 = colBase + nBase + nt*8 + tg*2;
                *(float2*)&C[(size_t) r0   *N + c0] = make_float2(acc[mt][nt][0], acc[mt][nt][1]);
                *(float2*)&C[(size_t)(r0+8)*N + c0] = make_float2(acc[mt][nt][2], acc[mt][nt][3]);
            }
        }
    } else {
        // fused qkv epilogue. Warp's 64 cols = exactly one head of q, k, or v.
        const int region = colBase >> 10;            // 0=q 1=k 2=v
        float* dst = (region == 0) ? g_qf : (region == 1 ? g_kf : g_v);
        const int head = (((colBase & 1023) + nBase) >> 6);
        #pragma unroll
        for (int mt = 0; mt < 2; mt++) {
            #pragma unroll
            for (int half = 0; half < 2; half++) {
                const int row = rowBase + mBase + mt*16 + g + half*8;
                const int t = row & (T_-1);
                const int b = row >> 12;
                const size_t obase = ((size_t)(b*H_ + head)*T_ + t)*HD;
                #pragma unroll
                for (int nt = 0; nt < 4; nt++) {
                    const int i0 = nt*8 + tg*2;
                    const float a0 = acc[mt][nt  ][half*2+0];
                    const float a1 = acc[mt][nt  ][half*2+1];
                    const float b0 = acc[mt][nt+4][half*2+0];
                    const float b1 = acc[mt][nt+4][half*2+1];
                    if (region == 2) {
                        *(float2*)&dst[obase + i0]      = make_float2(a0, a1);
                        *(float2*)&dst[obase + i0 + 32] = make_float2(b0, b1);
                    } else {
                        const float2 cc = *(const float2*)&g_cos[t*32 + i0];
                        const float2 ss = *(const float2*)&g_sin[t*32 + i0];
                        float r10 = a0*cc.x - b0*ss.x, r20 = b0*cc.x + a0*ss.x;
                        float r11 = a1*cc.y - b1*ss.y, r21 = b1*cc.y + a1*ss.y;
                        if (region == 0) {
                            r10 *= 0.125f; r20 *= 0.125f; r11 *= 0.125f; r21 *= 0.125f;
                        }
                        *(float2*)&dst[obase + i0]      = make_float2(elu1(r10), elu1(r11));
                        *(float2*)&dst[obase + i0 + 32] = make_float2(elu1(r20), elu1(r21));
                    }
                }
            }
        }
    }
}

// ---------------------------------------------------------------------------
__global__ void rope_table_kernel() {
    int idx = blockIdx.x * blockDim.x + threadIdx.x;
    if (idx >= T_*32) return;
    int t = idx >> 5;
    int i = idx & 31;
    double inv = pow(500000.0, -(double)(2*i) / 64.0);
    double a = (double)t * inv;
    g_cos[idx] = (float)cos(a);
    g_sin[idx] = (float)sin(a);
}

__global__ __launch_bounds__(256)
void round_x_kernel(const float* __restrict__ x) {
    int i = blockIdx.x * 256 + threadIdx.x;
    float4 v = ((const float4*)x)[i];
    v.x = tf32r(v.x); v.y = tf32r(v.y); v.z = tf32r(v.z); v.w = tf32r(v.w);
    ((float4*)g_xa)[i] = v;
}

__global__ __launch_bounds__(256)
void transpose_round_kernel(const float* __restrict__ in, float* __restrict__ out,
                            int R, int Cc) {
    __shared__ float tile[32][33];
    int bx = blockIdx.x * 32, by = blockIdx.y * 32;
    int tx = threadIdx.x, ty = threadIdx.y;
    #pragma unroll
    for (int i = 0; i < 32; i += 8)
        tile[ty + i][tx] = in[(size_t)(by + ty + i) * Cc + bx + tx];
    __syncthreads();
    #pragma unroll
    for (int i = 0; i < 32; i += 8)
        out[(size_t)(bx + ty + i) * R + by + tx] = tf32r(tile[tx][ty + i]);
}

// ---------------------------------------------------------------------------
// kv partial accumulation: 64 threads, 8x8 register microtile per thread.
// ---------------------------------------------------------------------------
__global__ __launch_bounds__(64)
void kv_accum_kernel() {
    int blk = blockIdx.x;
    int bh  = blk >> 4;
    int c   = blk & 15;
    int tid = threadIdx.x;
    int d0  = (tid >> 3) * 8;
    int j0  = (tid & 7) * 8;

    __shared__ float kb[16][64];
    __shared__ float vb[16][64];

    float acc[8][8] = {};
    float ks[8] = {};

    int t0 = c * CHLEN;
    for (int tb = 0; tb < CHLEN; tb += 16) {
        #pragma unroll
        for (int u = 0; u < 4; u++) {
            int f  = tid + u*64;
            int rr = f >> 4, c4 = f & 15;
            int t  = t0 + tb + rr;
            *(float4*)&kb[rr][c4*4] =
                *(const float4*)&g_kf[((size_t)bh*T_ + t)*HD + c4*4];
            *(float4*)&vb[rr][c4*4] =
                *(const float4*)&g_v[((size_t)bh*T_ + t)*HD + c4*4];
        }
        __syncthreads();
        #pragma unroll
        for (int tt = 0; tt < 16; tt++) {
            float kk[8], vv[8];
            *(float4*)&kk[0] = *(float4*)&kb[tt][d0];
            *(float4*)&kk[4] = *(float4*)&kb[tt][d0+4];
            *(float4*)&vv[0] = *(float4*)&vb[tt][j0];
            *(float4*)&vv[4] = *(float4*)&vb[tt][j0+4];
            #pragma unroll
            for (int i = 0; i < 8; i++) {
                ks[i] += kk[i];
                #pragma unroll
                for (int j = 0; j < 8; j++)
                    acc[i][j] += kk[i] * vv[j];
            }
        }
        __syncthreads();
    }

    #pragma unroll
    for (int i = 0; i < 8; i++) {
        float* p = &g_kvp[((size_t)(c*BH + bh)*HD + d0 + i)*HD + j0];
        #pragma unroll
        for (int j4 = 0; j4 < 2; j4++)
            *(float4*)&p[j4*4] = make_float4(acc[i][j4*4+0], acc[i][j4*4+1],
                                             acc[i][j4*4+2], acc[i][j4*4+3]);
    }
    if ((tid & 7) == 0) {
        #pragma unroll
        for (int i = 0; i < 8; i++)
            g_ksp[(c*BH + bh)*HD + d0 + i] = ks[i];
    }
}

__global__ void kv_reduce_kernel() {
    int idx = blockIdx.x * 256 + threadIdx.x;
    if (idx < BH*HD*HD) {
        float s = 0.f;
        #pragma unroll
        for (int c = 0; c < NCHUNK; c++) s += g_kvp[(size_t)c*BH*HD*HD + idx];
        g_kv[idx] = s;
    }
    if (idx < BH*HD) {
        float s = 0.f;
        #pragma unroll
        for (int c = 0; c < NCHUNK; c++) s += g_ksp[c*BH*HD + idx];
        g_ksum[idx] = s;
    }
}

// ---------------------------------------------------------------------------
// attention epilogue -> g_attn (tf32-rounded, feeds GEMM2)
// ---------------------------------------------------------------------------
__global__ __launch_bounds__(256)
void attn_out_kernel() {
    int blk = blockIdx.x;
    int bh  = blk >> 6;
    int tc  = blk & 63;
    int b   = bh >> 4;
    int h   = bh & 15;
    int tid = threadIdx.x;

    __shared__ float skv[HD*HD];
    __shared__ float sks[HD];
    __shared__ float sqf[64*HD];

    #pragma unroll
    for (int u = 0; u < 16; u++) {
        int li = tid + u*256;
        skv[li] = g_kv[bh*HD*HD + li];
        sqf[li] = g_qf[((size_t)bh*T_ + tc*64)*HD + li];
    }
    if (tid < 64) sks[tid] = g_ksum[bh*HD + tid];
    __syncthreads();

    int tl = tid >> 2;
    int jb = (tid & 3) << 4;

    float den = 0.f;
    #pragma unroll
    for (int dd = 0; dd < 64; dd++) den += sqf[tl*64 + dd] * sks[dd];
    float sc = 1.f / fmaxf(den, 1e-6f);

    float4 acc[4] = {};
    #pragma unroll
    for (int dd = 0; dd < 64; dd++) {
        float qd = sqf[tl*64 + dd];
        const float4* kvr = (const float4*)&skv[dd*64 + jb];
        #pragma unroll
        for (int j4 = 0; j4 < 4; j4++) {
            float4 kk = kvr[j4];
            acc[j4].x += qd * kk.x;
            acc[j4].y += qd * kk.y;
            acc[j4].z += qd * kk.z;
            acc[j4].w += qd * kk.w;
        }
    }

    int t = tc*64 + tl;
    float* outp = &g_attn[((size_t)(b*T_ + t))*D_ + h*HD + jb];
    #pragma unroll
    for (int j4 = 0; j4 < 4; j4++) {
        float4 v = make_float4(tf32r(acc[j4].x*sc), tf32r(acc[j4].y*sc),
                               tf32r(acc[j4].z*sc), tf32r(acc[j4].w*sc));
        *(float4*)&outp[j4*4] = v;
    }
}

// ---------------------------------------------------------------------------
extern "C" void kernel_launch(void* const* d_in, const int* in_sizes, int n_in,
                              void* d_out, int out_size) {
    const float* x = nullptr; const float* Wqkv = nullptr; const float* Wout = nullptr;
    for (int i = 0; i < n_in; i++) {
        if (in_sizes[i] == BT*D_)       x    = (const float*)d_in[i];
        else if (in_sizes[i] == D_*NKV) Wqkv = (const float*)d_in[i];
        else if (in_sizes[i] == D_*D_)  Wout = (const float*)d_in[i];
    }
    float* out = (float*)d_out;

    float *attn_p, *xa_p, *wqT_p, *woT_p;
    cudaGetSymbolAddress((void**)&attn_p, g_attn);
    cudaGetSymbolAddress((void**)&xa_p,   g_xa);
    cudaGetSymbolAddress((void**)&wqT_p,  g_wqT);
    cudaGetSymbolAddress((void**)&woT_p,  g_woT);

    cudaFuncSetAttribute(gemm_tf32_kernel,
                         cudaFuncAttributeMaxDynamicSharedMemorySize, GEMM_SMEM);

    // 1. RoPE tables + input prep
    rope_table_kernel<<<(T_*32 + 255)/256, 256>>>();
    round_x_kernel<<<(BT*D_/4)/256, 256>>>(x);
    {
        dim3 blk(32, 8);
        transpose_round_kernel<<<dim3(NKV/32, D_/32), blk>>>(Wqkv, wqT_p, D_, NKV);
        transpose_round_kernel<<<dim3(D_/32,  D_/32), blk>>>(Wout, woT_p, D_, D_);
    }

    // 2. qkv GEMM with fused RoPE + feature-map epilogue (no qkv buffer!)
    gemm_tf32_kernel<<<dim3(NKV/128, BT/128), 256, GEMM_SMEM>>>(NKV, 1, xa_p, wqT_p, nullptr);

    // 3. kv & ksum
    kv_accum_kernel<<<BH*NCHUNK, 64>>>();
    kv_reduce_kernel<<<(BH*HD*HD)/256, 256>>>();

    // 4. attention epilogue
    attn_out_kernel<<<BH*64, 256>>>();

    // 5. out = attn @ W_out
    gemm_tf32_kernel<<<dim3(D_/128, BT/128), 256, GEMM_SMEM>>>(D_, 0, attn_p, woT_p, out);
}